// round 11
// baseline (speedup 1.0000x reference)
#include <cuda_runtime.h>
#include <cuda_bf16.h>
#include <cstdint>
#include <cstddef>

// ScaledDotProductAttention B=32,S=2048,D=64 fp32 via mma.sync bf16-split.
// out = [context (B,S,D) | attn (B,S,S)] fp32.
// R10 = R6 champion + fused in-kernel attn normalization (no second kernel)
//       + GEMM1 accumulator split for HMMA ILP.

namespace {
constexpr int B_ = 32, S_ = 2048, D_ = 64;
constexpr int TQ = 128;            // q rows per CTA
constexpr int TK = 128;            // k cols per tile
constexpr int NT = 256;            // 8 warps; warp w owns q rows w*16..w*16+15
constexpr int NKT = S_ / TK;       // 16
constexpr size_t CTX_ELEMS = (size_t)B_ * S_ * D_;
constexpr float QSCALE = 0.125f * 1.4426950408889634f;   // 1/sqrt(64) * log2(e)

// smem: six 16KB tiles (128 rows x 128B bf16, swizzled)
constexpr int SM_QHI = 0;
constexpr int SM_QLO = 16384;
constexpr int SM_KHI = 32768;
constexpr int SM_KLO = 49152;
constexpr int SM_VHI = 65536;
constexpr int SM_VLO = 81920;
constexpr int SMEM_TOTAL = 98304;  // 96KB -> 2 CTAs/SM (192KB < 228KB)
}

__device__ __forceinline__ uint32_t smem_u32(const void* p) {
    uint32_t a;
    asm("{ .reg .u64 t; cvta.to.shared.u64 t, %1; cvt.u32.u64 %0, t; }" : "=r"(a) : "l"(p));
    return a;
}
__device__ __forceinline__ uint32_t swz(uint32_t off) { return off ^ ((off >> 3) & 0x70); }
__device__ __forceinline__ float ex2(float x) {
    float r;
    asm("ex2.approx.f32 %0, %1;" : "=f"(r) : "f"(x));
    return r;
}

__device__ __forceinline__ void mma_bf16(float c[4], uint32_t a0, uint32_t a1,
                                         uint32_t a2, uint32_t a3,
                                         uint32_t b0, uint32_t b1) {
    asm volatile(
        "mma.sync.aligned.m16n8k16.row.col.f32.bf16.bf16.f32 "
        "{%0,%1,%2,%3},{%4,%5,%6,%7},{%8,%9},{%0,%1,%2,%3};"
        : "+f"(c[0]), "+f"(c[1]), "+f"(c[2]), "+f"(c[3])
        : "r"(a0), "r"(a1), "r"(a2), "r"(a3), "r"(b0), "r"(b1));
}
__device__ __forceinline__ void ldmat4(uint32_t r[4], uint32_t addr) {
    asm volatile("ldmatrix.sync.aligned.m8n8.x4.shared.b16 {%0,%1,%2,%3},[%4];"
                 : "=r"(r[0]), "=r"(r[1]), "=r"(r[2]), "=r"(r[3]) : "r"(addr));
}
__device__ __forceinline__ void ldmat4t(uint32_t r[4], uint32_t addr) {
    asm volatile("ldmatrix.sync.aligned.m8n8.x4.trans.shared.b16 {%0,%1,%2,%3},[%4];"
                 : "=r"(r[0]), "=r"(r[1]), "=r"(r[2]), "=r"(r[3]) : "r"(addr));
}

__device__ __forceinline__ void bf_split(float x, uint16_t& h, uint16_t& l) {
    __nv_bfloat16 bh = __float2bfloat16(x);
    float r = x - __bfloat162float(bh);
    h = __bfloat16_as_ushort(bh);
    l = __bfloat16_as_ushort(__float2bfloat16(r));
}

// Stage [128 rows x 64 f32] gmem tile -> two bf16 smem tiles (natural, swizzled)
__device__ __forceinline__ void stage_split(const float* __restrict__ g, char* smem,
                                            int hi_off, int lo_off, int t, float scale) {
    const float4* g4 = reinterpret_cast<const float4*>(g);
    #pragma unroll
    for (int i = 0; i < 8; i++) {
        int idx = t + i * NT;            // 2048 float4s: 128 rows x 16
        int row = idx >> 4;
        int c4  = idx & 15;
        float4 v = g4[idx];
        v.x *= scale; v.y *= scale; v.z *= scale; v.w *= scale;
        uint16_t h0,l0,h1,l1,h2,l2,h3,l3;
        bf_split(v.x,h0,l0); bf_split(v.y,h1,l1); bf_split(v.z,h2,l2); bf_split(v.w,h3,l3);
        uint2 hp = { (uint32_t)h0 | ((uint32_t)h1 << 16), (uint32_t)h2 | ((uint32_t)h3 << 16) };
        uint2 lp = { (uint32_t)l0 | ((uint32_t)l1 << 16), (uint32_t)l2 | ((uint32_t)l3 << 16) };
        uint32_t off = swz((uint32_t)(row * 128 + c4 * 8));
        *reinterpret_cast<uint2*>(smem + hi_off + off) = hp;
        *reinterpret_cast<uint2*>(smem + lo_off + off) = lp;
    }
}

__global__ void __launch_bounds__(NT, 2)
attn_tc(const float* __restrict__ Q, const float* __restrict__ Kg,
        const float* __restrict__ V, const int* __restrict__ M,
        float* __restrict__ ctx, float* __restrict__ attn)
{
    extern __shared__ char smem[];
    const uint32_t sb = smem_u32(smem);
    const int b  = blockIdx.y;
    const int q0 = blockIdx.x * TQ;
    const int t  = threadIdx.x;
    const int w  = t >> 5, l = t & 31;
    const int m0 = w * 16;               // this warp's q-row base
    const int g  = l >> 2, tig = l & 3;  // quad row / col id

    // ---- stage Q (scale*log2e folded); Q smem idle after frag load
    stage_split(Q + ((size_t)b * S_ + q0) * D_, smem, SM_QHI, SM_QLO, t, QSCALE);
    __syncthreads();

    uint32_t qh[4][4], ql[4][4];
    {
        const int arow = m0 + (l & 15);
        const int acb  = (l >> 4) << 4;
        #pragma unroll
        for (int ks = 0; ks < 4; ks++) {
            uint32_t off = (uint32_t)arow * 128
                         + (((uint32_t)(ks * 32 + acb)) ^ ((uint32_t)(arow & 7) << 4));
            ldmat4(qh[ks], sb + SM_QHI + off);
            ldmat4(ql[ks], sb + SM_QLO + off);
        }
    }

    float cacc[8][4];
    #pragma unroll
    for (int i = 0; i < 8; i++) cacc[i][0] = cacc[i][1] = cacc[i][2] = cacc[i][3] = 0.f;
    float rta = 0.f, rtb = 0.f;

    const int rowA = q0 + m0 + g;
    const int rowB = rowA + 8;
    const int* mA = M + (size_t)(b * S_ + rowA) * S_;
    const int* mB = M + (size_t)(b * S_ + rowB) * S_;
    float* aA = attn + (size_t)(b * S_ + rowA) * S_;
    float* aB = attn + (size_t)(b * S_ + rowB) * S_;

    // fragment addressing constants
    const int brow = (l & 7) + ((l & 16) ? 8 : 0);
    const int bcb  = (l & 8) ? 16 : 0;
    const int vrow = (l & 7) + ((l & 8) ? 8 : 0);
    const int vcb  = (l & 16) ? 16 : 0;

    for (int kt = 0; kt < NKT; kt++) {
        const int k0 = kt * TK;
        __syncthreads();   // previous iteration's smem reads done
        stage_split(Kg + ((size_t)b * S_ + k0) * D_, smem, SM_KHI, SM_KLO, t, 1.f);
        stage_split(V  + ((size_t)b * S_ + k0) * D_, smem, SM_VHI, SM_VLO, t, 1.f);

        // ---- prefetch mask as packed bits (hides under staging/GEMM chunks)
        uint32_t mbA = 0, mbB = 0;
        #pragma unroll
        for (int nt = 0; nt < 16; nt++) {
            const int col = k0 + nt * 8 + tig * 2;
            const int2 ma = *reinterpret_cast<const int2*>(mA + col);
            const int2 mb = *reinterpret_cast<const int2*>(mB + col);
            if (ma.x) mbA |= 1u << (2 * nt);
            if (ma.y) mbA |= 1u << (2 * nt + 1);
            if (mb.x) mbB |= 1u << (2 * nt);
            if (mb.y) mbB |= 1u << (2 * nt + 1);
        }
        __syncthreads();

        float rpa = 0.f, rpb = 0.f;

        // ---- streamed: per 16-col chunk np: GEMM1 -> exp/STG -> pack -> GEMM2
        #pragma unroll
        for (int np = 0; np < 8; np++) {
            // GEMM1 chunk: K=64, 3 split passes; ql-pass in separate accums (ILP)
            float s0[4] = {0.f, 0.f, 0.f, 0.f};
            float s1[4] = {0.f, 0.f, 0.f, 0.f};
            float t0[4] = {0.f, 0.f, 0.f, 0.f};
            float t1[4] = {0.f, 0.f, 0.f, 0.f};
            #pragma unroll
            for (int ks = 0; ks < 4; ks++) {
                uint32_t off = (uint32_t)(np * 16 + brow) * 128
                             + (((uint32_t)(ks * 32 + bcb)) ^ ((uint32_t)(brow & 7) << 4));
                uint32_t bh[4], bl[4];
                ldmat4(bh, sb + SM_KHI + off);
                ldmat4(bl, sb + SM_KLO + off);
                mma_bf16(s0, qh[ks][0],qh[ks][1],qh[ks][2],qh[ks][3], bh[0],bh[1]);
                mma_bf16(s1, qh[ks][0],qh[ks][1],qh[ks][2],qh[ks][3], bh[2],bh[3]);
                mma_bf16(t0, ql[ks][0],ql[ks][1],ql[ks][2],ql[ks][3], bh[0],bh[1]);
                mma_bf16(t1, ql[ks][0],ql[ks][1],ql[ks][2],ql[ks][3], bh[2],bh[3]);
                mma_bf16(s0, qh[ks][0],qh[ks][1],qh[ks][2],qh[ks][3], bl[0],bl[1]);
                mma_bf16(s1, qh[ks][0],qh[ks][1],qh[ks][2],qh[ks][3], bl[2],bl[3]);
            }
            #pragma unroll
            for (int e = 0; e < 4; e++) { s0[e] += t0[e]; s1[e] += t1[e]; }

            // mask + exp2 + attn STG + rowsum (nt = 2np, 2np+1)
            const int col0 = k0 + (2 * np) * 8 + tig * 2;
            float p00 = (mbA >> (4*np))     & 1u ? 0.f : ex2(s0[0]);
            float p01 = (mbA >> (4*np + 1)) & 1u ? 0.f : ex2(s0[1]);
            float p02 = (mbB >> (4*np))     & 1u ? 0.f : ex2(s0[2]);
            float p03 = (mbB >> (4*np + 1)) & 1u ? 0.f : ex2(s0[3]);
            float p10 = (mbA >> (4*np + 2)) & 1u ? 0.f : ex2(s1[0]);
            float p11 = (mbA >> (4*np + 3)) & 1u ? 0.f : ex2(s1[1]);
            float p12 = (mbB >> (4*np + 2)) & 1u ? 0.f : ex2(s1[2]);
            float p13 = (mbB >> (4*np + 3)) & 1u ? 0.f : ex2(s1[3]);
            rpa += (p00 + p01) + (p10 + p11);
            rpb += (p02 + p03) + (p12 + p13);
            *reinterpret_cast<float2*>(aA + col0)     = make_float2(p00, p01);
            *reinterpret_cast<float2*>(aB + col0)     = make_float2(p02, p03);
            *reinterpret_cast<float2*>(aA + col0 + 8) = make_float2(p10, p11);
            *reinterpret_cast<float2*>(aB + col0 + 8) = make_float2(p12, p13);

            // pack P chunk (C-frag -> A-frag identity), hi/lo
            uint32_t phi[4], plo[4];
            {
                uint16_t h0,l0_,h1,l1_;
                bf_split(p00, h0, l0_); bf_split(p01, h1, l1_);
                phi[0] = (uint32_t)h0 | ((uint32_t)h1 << 16);
                plo[0] = (uint32_t)l0_ | ((uint32_t)l1_ << 16);
                bf_split(p02, h0, l0_); bf_split(p03, h1, l1_);
                phi[1] = (uint32_t)h0 | ((uint32_t)h1 << 16);
                plo[1] = (uint32_t)l0_ | ((uint32_t)l1_ << 16);
                bf_split(p10, h0, l0_); bf_split(p11, h1, l1_);
                phi[2] = (uint32_t)h0 | ((uint32_t)h1 << 16);
                plo[2] = (uint32_t)l0_ | ((uint32_t)l1_ << 16);
                bf_split(p12, h0, l0_); bf_split(p13, h1, l1_);
                phi[3] = (uint32_t)h0 | ((uint32_t)h1 << 16);
                plo[3] = (uint32_t)l0_ | ((uint32_t)l1_ << 16);
            }

            // GEMM2 chunk: ctx += P_chunk @ V[16 rows of this chunk]
            #pragma unroll
            for (int np2 = 0; np2 < 4; np2++) {
                uint32_t off = (uint32_t)(np * 16 + vrow) * 128
                             + (((uint32_t)(np2 * 32 + vcb)) ^ ((uint32_t)(vrow & 7) << 4));
                uint32_t vh[4], vl[4];
                ldmat4t(vh, sb + SM_VHI + off);
                ldmat4t(vl, sb + SM_VLO + off);
                mma_bf16(cacc[2*np2],   phi[0],phi[1],phi[2],phi[3], vh[0],vh[1]);
                mma_bf16(cacc[2*np2+1], phi[0],phi[1],phi[2],phi[3], vh[2],vh[3]);
                mma_bf16(cacc[2*np2],   phi[0],phi[1],phi[2],phi[3], vl[0],vl[1]);
                mma_bf16(cacc[2*np2+1], phi[0],phi[1],phi[2],phi[3], vl[2],vl[3]);
                mma_bf16(cacc[2*np2],   plo[0],plo[1],plo[2],plo[3], vh[0],vh[1]);
                mma_bf16(cacc[2*np2+1], plo[0],plo[1],plo[2],plo[3], vh[2],vh[3]);
            }
        }

        rpa += __shfl_xor_sync(0xffffffffu, rpa, 1);
        rpa += __shfl_xor_sync(0xffffffffu, rpa, 2);
        rpb += __shfl_xor_sync(0xffffffffu, rpb, 1);
        rpb += __shfl_xor_sync(0xffffffffu, rpb, 2);
        rta += rpa; rtb += rpb;
    }

    // ---- finalize: normalize ctx
    const float inva = 1.0f / rta, invb = 1.0f / rtb;
    float* cA = ctx + (size_t)(b * S_ + rowA) * D_;
    float* cB = ctx + (size_t)(b * S_ + rowB) * D_;
    #pragma unroll
    for (int nt = 0; nt < 8; nt++) {
        const int col = nt * 8 + tig * 2;
        *reinterpret_cast<float2*>(cA + col) = make_float2(cacc[nt][0] * inva, cacc[nt][1] * inva);
        *reinterpret_cast<float2*>(cB + col) = make_float2(cacc[nt][2] * invb, cacc[nt][3] * invb);
    }

    // ---- fused attn normalization: each thread rescales exactly the float2
    //      words it wrote (same-thread RAW; mostly L2 hits on the fresh slab)
    #pragma unroll 1
    for (int kt = 0; kt < NKT; kt++) {
        const int base = kt * TK + tig * 2;
        #pragma unroll
        for (int nt = 0; nt < 16; nt++) {
            const int col = base + nt * 8;
            float2 va = *reinterpret_cast<float2*>(aA + col);
            float2 vb = *reinterpret_cast<float2*>(aB + col);
            va.x *= inva; va.y *= inva;
            vb.x *= invb; vb.y *= invb;
            *reinterpret_cast<float2*>(aA + col) = va;
            *reinterpret_cast<float2*>(aB + col) = vb;
        }
    }
}

extern "C" void kernel_launch(void* const* d_in, const int* in_sizes, int n_in,
                              void* d_out, int out_size)
{
    const float* Q = (const float*)d_in[0];
    const float* K = (const float*)d_in[1];
    const float* V = (const float*)d_in[2];
    const int*   M = (const int*)d_in[3];
    float* ctx  = (float*)d_out;
    float* attn = (float*)d_out + CTX_ELEMS;

    cudaFuncSetAttribute(attn_tc, cudaFuncAttributeMaxDynamicSharedMemorySize, SMEM_TOTAL);

    dim3 grid(S_ / TQ, B_);
    attn_tc<<<grid, NT, SMEM_TOTAL>>>(Q, K, V, M, ctx, attn);
}

// round 12
// speedup vs baseline: 1.2346x; 1.2346x over previous
#include <cuda_runtime.h>
#include <cuda_bf16.h>
#include <cstdint>
#include <cstddef>

// ScaledDotProductAttention B=32,S=2048,D=64 fp32 via mma.sync bf16-split.
// out = [context (B,S,D) | attn (B,S,S)] fp32.
// R12 = R6 champion + GEMM1 4-chain split + b-frag prefetch + pointer diet.

namespace {
constexpr int B_ = 32, S_ = 2048, D_ = 64;
constexpr int TQ = 128;            // q rows per CTA
constexpr int TK = 128;            // k cols per tile
constexpr int NT = 256;            // 8 warps; warp w owns q rows w*16..w*16+15
constexpr int NKT = S_ / TK;       // 16
constexpr size_t CTX_ELEMS = (size_t)B_ * S_ * D_;
constexpr float QSCALE = 0.125f * 1.4426950408889634f;   // 1/sqrt(64) * log2(e)
constexpr int ROWB_OFF = 8 * S_;   // row g+8 offset in attn/mask row units

// smem: six 16KB tiles (128 rows x 128B bf16, swizzled)
constexpr int SM_QHI = 0;
constexpr int SM_QLO = 16384;
constexpr int SM_KHI = 32768;
constexpr int SM_KLO = 49152;
constexpr int SM_VHI = 65536;
constexpr int SM_VLO = 81920;
constexpr int SMEM_TOTAL = 98304;  // 96KB -> 2 CTAs/SM (192KB < 228KB)
}

__device__ float g_inv_rowsum[B_ * S_];

__device__ __forceinline__ uint32_t smem_u32(const void* p) {
    uint32_t a;
    asm("{ .reg .u64 t; cvta.to.shared.u64 t, %1; cvt.u32.u64 %0, t; }" : "=r"(a) : "l"(p));
    return a;
}
__device__ __forceinline__ uint32_t swz(uint32_t off) { return off ^ ((off >> 3) & 0x70); }
__device__ __forceinline__ float ex2(float x) {
    float r;
    asm("ex2.approx.f32 %0, %1;" : "=f"(r) : "f"(x));
    return r;
}

__device__ __forceinline__ void mma_bf16(float c[4], uint32_t a0, uint32_t a1,
                                         uint32_t a2, uint32_t a3,
                                         uint32_t b0, uint32_t b1) {
    asm volatile(
        "mma.sync.aligned.m16n8k16.row.col.f32.bf16.bf16.f32 "
        "{%0,%1,%2,%3},{%4,%5,%6,%7},{%8,%9},{%0,%1,%2,%3};"
        : "+f"(c[0]), "+f"(c[1]), "+f"(c[2]), "+f"(c[3])
        : "r"(a0), "r"(a1), "r"(a2), "r"(a3), "r"(b0), "r"(b1));
}
__device__ __forceinline__ void ldmat4(uint32_t r[4], uint32_t addr) {
    asm volatile("ldmatrix.sync.aligned.m8n8.x4.shared.b16 {%0,%1,%2,%3},[%4];"
                 : "=r"(r[0]), "=r"(r[1]), "=r"(r[2]), "=r"(r[3]) : "r"(addr));
}
__device__ __forceinline__ void ldmat4t(uint32_t r[4], uint32_t addr) {
    asm volatile("ldmatrix.sync.aligned.m8n8.x4.trans.shared.b16 {%0,%1,%2,%3},[%4];"
                 : "=r"(r[0]), "=r"(r[1]), "=r"(r[2]), "=r"(r[3]) : "r"(addr));
}

__device__ __forceinline__ void bf_split(float x, uint16_t& h, uint16_t& l) {
    __nv_bfloat16 bh = __float2bfloat16(x);
    float r = x - __bfloat162float(bh);
    h = __bfloat16_as_ushort(bh);
    l = __bfloat16_as_ushort(__float2bfloat16(r));
}

// Stage [128 rows x 64 f32] gmem tile -> two bf16 smem tiles (natural, swizzled)
__device__ __forceinline__ void stage_split(const float* __restrict__ g, char* smem,
                                            int hi_off, int lo_off, int t, float scale) {
    const float4* g4 = reinterpret_cast<const float4*>(g);
    #pragma unroll
    for (int i = 0; i < 8; i++) {
        int idx = t + i * NT;            // 2048 float4s: 128 rows x 16
        int row = idx >> 4;
        int c4  = idx & 15;
        float4 v = g4[idx];
        v.x *= scale; v.y *= scale; v.z *= scale; v.w *= scale;
        uint16_t h0,l0,h1,l1,h2,l2,h3,l3;
        bf_split(v.x,h0,l0); bf_split(v.y,h1,l1); bf_split(v.z,h2,l2); bf_split(v.w,h3,l3);
        uint2 hp = { (uint32_t)h0 | ((uint32_t)h1 << 16), (uint32_t)h2 | ((uint32_t)h3 << 16) };
        uint2 lp = { (uint32_t)l0 | ((uint32_t)l1 << 16), (uint32_t)l2 | ((uint32_t)l3 << 16) };
        uint32_t off = swz((uint32_t)(row * 128 + c4 * 8));
        *reinterpret_cast<uint2*>(smem + hi_off + off) = hp;
        *reinterpret_cast<uint2*>(smem + lo_off + off) = lp;
    }
}

__global__ void __launch_bounds__(NT, 2)
attn_tc(const float* __restrict__ Q, const float* __restrict__ Kg,
        const float* __restrict__ V, const int* __restrict__ M,
        float* __restrict__ ctx, float* __restrict__ attn)
{
    extern __shared__ char smem[];
    const uint32_t sb = smem_u32(smem);
    const int b  = blockIdx.y;
    const int q0 = blockIdx.x * TQ;
    const int t  = threadIdx.x;
    const int w  = t >> 5, l = t & 31;
    const int m0 = w * 16;               // this warp's q-row base
    const int g  = l >> 2, tig = l & 3;  // quad row / col id

    // ---- stage Q (scale*log2e folded); Q smem idle after frag load
    stage_split(Q + ((size_t)b * S_ + q0) * D_, smem, SM_QHI, SM_QLO, t, QSCALE);
    __syncthreads();

    uint32_t qh[4][4], ql[4][4];
    {
        const int arow = m0 + (l & 15);
        const int acb  = (l >> 4) << 4;
        #pragma unroll
        for (int ks = 0; ks < 4; ks++) {
            uint32_t off = (uint32_t)arow * 128
                         + (((uint32_t)(ks * 32 + acb)) ^ ((uint32_t)(arow & 7) << 4));
            ldmat4(qh[ks], sb + SM_QHI + off);
            ldmat4(ql[ks], sb + SM_QLO + off);
        }
    }

    float cacc[8][4];
    #pragma unroll
    for (int i = 0; i < 8; i++) cacc[i][0] = cacc[i][1] = cacc[i][2] = cacc[i][3] = 0.f;
    float rta = 0.f, rtb = 0.f;

    const int rowA = q0 + m0 + g;        // rowB = rowA + 8 (via ROWB_OFF in elements)
    const int* mA = M + (size_t)(b * S_ + rowA) * S_;
    float* aA = attn + (size_t)(b * S_ + rowA) * S_;

    // fragment addressing constants
    const int brow = (l & 7) + ((l & 16) ? 8 : 0);
    const int bcb  = (l & 8) ? 16 : 0;
    const int vrow = (l & 7) + ((l & 8) ? 8 : 0);
    const int vcb  = (l & 16) ? 16 : 0;

    for (int kt = 0; kt < NKT; kt++) {
        const int k0 = kt * TK;
        __syncthreads();   // previous iteration's smem reads done
        stage_split(Kg + ((size_t)b * S_ + k0) * D_, smem, SM_KHI, SM_KLO, t, 1.f);
        stage_split(V  + ((size_t)b * S_ + k0) * D_, smem, SM_VHI, SM_VLO, t, 1.f);

        // ---- prefetch mask as packed bits (hides under staging/GEMM chunks)
        uint32_t mbA = 0, mbB = 0;
        #pragma unroll
        for (int nt = 0; nt < 16; nt++) {
            const int col = k0 + nt * 8 + tig * 2;
            const int2 ma = *reinterpret_cast<const int2*>(mA + col);
            const int2 mb = *reinterpret_cast<const int2*>(mA + col + ROWB_OFF);
            if (ma.x) mbA |= 1u << (2 * nt);
            if (ma.y) mbA |= 1u << (2 * nt + 1);
            if (mb.x) mbB |= 1u << (2 * nt);
            if (mb.y) mbB |= 1u << (2 * nt + 1);
        }
        __syncthreads();

        float rpa = 0.f, rpb = 0.f;

        // ---- streamed: per 16-col chunk np: GEMM1 -> exp/STG -> pack -> GEMM2
        #pragma unroll
        for (int np = 0; np < 8; np++) {
            // prefetch all 8 b-fragments back-to-back (MLP), then run MMA chains
            uint32_t bh[4][4], bl[4][4];
            #pragma unroll
            for (int ks = 0; ks < 4; ks++) {
                uint32_t off = (uint32_t)(np * 16 + brow) * 128
                             + (((uint32_t)(ks * 32 + bcb)) ^ ((uint32_t)(brow & 7) << 4));
                ldmat4(bh[ks], sb + SM_KHI + off);
                ldmat4(bl[ks], sb + SM_KLO + off);
            }
            // GEMM1 chunk: K=64, 3 split passes in 4 independent chains
            float s0[4] = {0.f, 0.f, 0.f, 0.f};
            float s1[4] = {0.f, 0.f, 0.f, 0.f};
            float t0[4] = {0.f, 0.f, 0.f, 0.f};
            float t1[4] = {0.f, 0.f, 0.f, 0.f};
            #pragma unroll
            for (int ks = 0; ks < 4; ks++) {
                mma_bf16(s0, qh[ks][0],qh[ks][1],qh[ks][2],qh[ks][3], bh[ks][0],bh[ks][1]);
                mma_bf16(s1, qh[ks][0],qh[ks][1],qh[ks][2],qh[ks][3], bh[ks][2],bh[ks][3]);
                mma_bf16(t0, ql[ks][0],ql[ks][1],ql[ks][2],ql[ks][3], bh[ks][0],bh[ks][1]);
                mma_bf16(t1, ql[ks][0],ql[ks][1],ql[ks][2],ql[ks][3], bh[ks][2],bh[ks][3]);
                mma_bf16(s0, qh[ks][0],qh[ks][1],qh[ks][2],qh[ks][3], bl[ks][0],bl[ks][1]);
                mma_bf16(s1, qh[ks][0],qh[ks][1],qh[ks][2],qh[ks][3], bl[ks][2],bl[ks][3]);
            }
            #pragma unroll
            for (int e = 0; e < 4; e++) { s0[e] += t0[e]; s1[e] += t1[e]; }

            // mask + exp2 + attn STG + rowsum (nt = 2np, 2np+1)
            const int col0 = k0 + (2 * np) * 8 + tig * 2;
            float p00 = (mbA >> (4*np))     & 1u ? 0.f : ex2(s0[0]);
            float p01 = (mbA >> (4*np + 1)) & 1u ? 0.f : ex2(s0[1]);
            float p02 = (mbB >> (4*np))     & 1u ? 0.f : ex2(s0[2]);
            float p03 = (mbB >> (4*np + 1)) & 1u ? 0.f : ex2(s0[3]);
            float p10 = (mbA >> (4*np + 2)) & 1u ? 0.f : ex2(s1[0]);
            float p11 = (mbA >> (4*np + 3)) & 1u ? 0.f : ex2(s1[1]);
            float p12 = (mbB >> (4*np + 2)) & 1u ? 0.f : ex2(s1[2]);
            float p13 = (mbB >> (4*np + 3)) & 1u ? 0.f : ex2(s1[3]);
            rpa += (p00 + p01) + (p10 + p11);
            rpb += (p02 + p03) + (p12 + p13);
            *reinterpret_cast<float2*>(aA + col0)                = make_float2(p00, p01);
            *reinterpret_cast<float2*>(aA + col0 + ROWB_OFF)     = make_float2(p02, p03);
            *reinterpret_cast<float2*>(aA + col0 + 8)            = make_float2(p10, p11);
            *reinterpret_cast<float2*>(aA + col0 + 8 + ROWB_OFF) = make_float2(p12, p13);

            // pack P chunk (C-frag -> A-frag identity), hi/lo
            uint32_t phi[4], plo[4];
            {
                uint16_t h0,l0_,h1,l1_;
                bf_split(p00, h0, l0_); bf_split(p01, h1, l1_);
                phi[0] = (uint32_t)h0 | ((uint32_t)h1 << 16);
                plo[0] = (uint32_t)l0_ | ((uint32_t)l1_ << 16);
                bf_split(p02, h0, l0_); bf_split(p03, h1, l1_);
                phi[1] = (uint32_t)h0 | ((uint32_t)h1 << 16);
                plo[1] = (uint32_t)l0_ | ((uint32_t)l1_ << 16);
                bf_split(p10, h0, l0_); bf_split(p11, h1, l1_);
                phi[2] = (uint32_t)h0 | ((uint32_t)h1 << 16);
                plo[2] = (uint32_t)l0_ | ((uint32_t)l1_ << 16);
                bf_split(p12, h0, l0_); bf_split(p13, h1, l1_);
                phi[3] = (uint32_t)h0 | ((uint32_t)h1 << 16);
                plo[3] = (uint32_t)l0_ | ((uint32_t)l1_ << 16);
            }

            // GEMM2 chunk: ctx += P_chunk @ V[16 rows of this chunk]
            #pragma unroll
            for (int np2 = 0; np2 < 4; np2++) {
                uint32_t off = (uint32_t)(np * 16 + vrow) * 128
                             + (((uint32_t)(np2 * 32 + vcb)) ^ ((uint32_t)(vrow & 7) << 4));
                uint32_t vh[4], vl[4];
                ldmat4t(vh, sb + SM_VHI + off);
                ldmat4t(vl, sb + SM_VLO + off);
                mma_bf16(cacc[2*np2],   phi[0],phi[1],phi[2],phi[3], vh[0],vh[1]);
                mma_bf16(cacc[2*np2+1], phi[0],phi[1],phi[2],phi[3], vh[2],vh[3]);
                mma_bf16(cacc[2*np2],   phi[0],phi[1],phi[2],phi[3], vl[0],vl[1]);
                mma_bf16(cacc[2*np2+1], phi[0],phi[1],phi[2],phi[3], vl[2],vl[3]);
                mma_bf16(cacc[2*np2],   plo[0],plo[1],plo[2],plo[3], vh[0],vh[1]);
                mma_bf16(cacc[2*np2+1], plo[0],plo[1],plo[2],plo[3], vh[2],vh[3]);
            }
        }

        rpa += __shfl_xor_sync(0xffffffffu, rpa, 1);
        rpa += __shfl_xor_sync(0xffffffffu, rpa, 2);
        rpb += __shfl_xor_sync(0xffffffffu, rpb, 1);
        rpb += __shfl_xor_sync(0xffffffffu, rpb, 2);
        rta += rpa; rtb += rpb;
    }

    // ---- finalize: normalize ctx, write inv rowsums
    const float inva = 1.0f / rta, invb = 1.0f / rtb;
    if (tig == 0) {
        g_inv_rowsum[b * S_ + rowA]     = inva;
        g_inv_rowsum[b * S_ + rowA + 8] = invb;
    }
    float* cA = ctx + (size_t)(b * S_ + rowA) * D_;
    #pragma unroll
    for (int nt = 0; nt < 8; nt++) {
        const int col = nt * 8 + tig * 2;
        *reinterpret_cast<float2*>(cA + col)          = make_float2(cacc[nt][0] * inva, cacc[nt][1] * inva);
        *reinterpret_cast<float2*>(cA + col + 8 * D_) = make_float2(cacc[nt][2] * invb, cacc[nt][3] * invb);
    }
}

// Rescale attn by 1/rowsum (~82% DRAM — at roofline).
__global__ void __launch_bounds__(256)
attn_normalize(float* __restrict__ attn)
{
    size_t i = (size_t)blockIdx.x * blockDim.x + threadIdx.x;   // float4 index
    float4* a4 = reinterpret_cast<float4*>(attn);
    const float inv = g_inv_rowsum[i >> 9];                     // 512 f4 per row
    float4 v = a4[i];
    v.x *= inv; v.y *= inv; v.z *= inv; v.w *= inv;
    a4[i] = v;
}

extern "C" void kernel_launch(void* const* d_in, const int* in_sizes, int n_in,
                              void* d_out, int out_size)
{
    const float* Q = (const float*)d_in[0];
    const float* K = (const float*)d_in[1];
    const float* V = (const float*)d_in[2];
    const int*   M = (const int*)d_in[3];
    float* ctx  = (float*)d_out;
    float* attn = (float*)d_out + CTX_ELEMS;

    cudaFuncSetAttribute(attn_tc, cudaFuncAttributeMaxDynamicSharedMemorySize, SMEM_TOTAL);

    dim3 grid(S_ / TQ, B_);
    attn_tc<<<grid, NT, SMEM_TOTAL>>>(Q, K, V, M, ctx, attn);

    const int n4 = (int)((size_t)B_ * S_ * S_ / 4 / 256);
    attn_normalize<<<n4, 256>>>(attn);
}